// round 7
// baseline (speedup 1.0000x reference)
#include <cuda_runtime.h>

#define NPIX 1024
#define NVCH 64
#define RB 64           // output rows per conv block (RB+6 = 70 = 5*14 steps)

__device__ float g_cube[(size_t)NVCH * NPIX * NPIX];   // 256 MB scratch
__device__ float g_g1d[8];

// ---------------------------------------------------------------- zero cube
__global__ __launch_bounds__(256) void zero_k() {
    float4* p = reinterpret_cast<float4*>(g_cube);
    const int n4 = NVCH * NPIX * NPIX / 4;
    float4 z = make_float4(0.f, 0.f, 0.f, 0.f);
    for (int i = blockIdx.x * 256 + threadIdx.x; i < n4; i += gridDim.x * 256)
        p[i] = z;
}

// ------------------------------------------------- recover separable 1D taps
__global__ void prep_k(const float* __restrict__ k2d) {
    int k = threadIdx.x;
    if (k < 7) {
        float s = 0.f;
        #pragma unroll
        for (int j = 0; j < 7; j++) s += k2d[k * 7 + j];
        g_g1d[k] = s;
    }
}

// ---------------------------------------------------------------- scatter
__global__ __launch_bounds__(256) void scatter_k(
    const float* __restrict__ pos,
    const float* __restrict__ vel,
    const float* __restrict__ flx,
    const float* __restrict__ vax,
    int M)
{
    int i = blockIdx.x * 256 + threadIdx.x;
    if (i >= M) return;

    float2 p = reinterpret_cast<const float2*>(pos)[i];
    float v  = vel[i];
    float f  = flx[i];

    float vel0 = __ldg(&vax[0]);
    float dv   = __fsub_rn(__ldg(&vax[1]), vel0);

    const float FOVH = 51.15f;
    int ix = (int)floorf(__fmul_rn(__fadd_rn(p.x, FOVH), 10.0f));
    int iy = (int)floorf(__fmul_rn(__fadd_rn(p.y, FOVH), 10.0f));
    int iv = (int)floorf(__fdiv_rn(__fsub_rn(v, vel0), dv));

    if ((unsigned)(ix + 4) >= (unsigned)(NPIX + 8)) return;
    if ((unsigned)(iy + 4) >= (unsigned)(NPIX + 8)) return;
    if ((unsigned)iv >= (unsigned)NVCH) return;

    int flat = (iv * NPIX + iy) * NPIX + ix;
    if ((unsigned)flat < (unsigned)(NVCH * NPIX * NPIX))
        atomicAdd(&g_cube[flat], f);
}

// -------- register-streaming separable 7x7 conv with depth-7 load prefetch
// p[7]: rolling ring of prefetched input rows (consumed 7 steps after issue).
// hb[2]: depth-1 prefetch of the warp-edge halo float4 (L1/L2-resident line).
// h[7]:  ring of horizontal results for the vertical pass.
// Chunk unroll = 14 so %7 and %2 ring indices are all compile-time.

#define VERT(JJ, comp)                                                        \
    (g0*h[((JJ)+1)%7].comp + g1*h[((JJ)+2)%7].comp + g2*h[((JJ)+3)%7].comp +  \
     g3*h[((JJ)+4)%7].comp + g4*h[((JJ)+5)%7].comp + g5*h[((JJ)+6)%7].comp +  \
     g6*h[(JJ)%7].comp)

#define CSTEP(J)                                                              \
{                                                                             \
    const int it = base + (J);                                                \
    const int yh = y0 - 3 + it;                                               \
    float4 a = p[(J) % 7];                                                    \
    /* prefetch main row it+7 into freed slot */                              \
    {                                                                         \
        int yn = yh + 7;                                                      \
        float4 np = make_float4(0.f, 0.f, 0.f, 0.f);                          \
        if ((it + 7 < RB + 6) && (unsigned)yn < (unsigned)NPIX)               \
            np = *(const float4*)(cube + (size_t)yn * NPIX + c);              \
        p[(J) % 7] = np;                                                      \
    }                                                                         \
    float4 hc = hb[(J) & 1];                                                  \
    /* prefetch halo for row it+1 */                                          \
    {                                                                         \
        int yn = yh + 1;                                                      \
        float4 nh = make_float4(0.f, 0.f, 0.f, 0.f);                          \
        if ((it + 1 < RB + 6) && (unsigned)yn < (unsigned)NPIX) {             \
            const float* rp = cube + (size_t)yn * NPIX;                       \
            if (lane == 0  && c >= 4)        nh = *(const float4*)(rp + c - 4);\
            if (lane == 31 && c + 7 < NPIX)  nh = *(const float4*)(rp + c + 4);\
        }                                                                     \
        hb[((J) + 1) & 1] = nh;                                               \
    }                                                                         \
    float lm1 = __shfl_up_sync(0xffffffffu, a.w, 1);                          \
    float lm2 = __shfl_up_sync(0xffffffffu, a.z, 1);                          \
    float lm3 = __shfl_up_sync(0xffffffffu, a.y, 1);                          \
    if (lane == 0)  { lm1 = hc.w; lm2 = hc.z; lm3 = hc.y; }                   \
    float rq1 = __shfl_down_sync(0xffffffffu, a.x, 1);                        \
    float rq2 = __shfl_down_sync(0xffffffffu, a.y, 1);                        \
    float rq3 = __shfl_down_sync(0xffffffffu, a.z, 1);                        \
    if (lane == 31) { rq1 = hc.x; rq2 = hc.y; rq3 = hc.z; }                   \
    float4 hx;                                                                \
    hx.x = lm3*g0 + lm2*g1 + lm1*g2 + a.x*g3 + a.y*g4 + a.z*g5 + a.w*g6;      \
    hx.y = lm2*g0 + lm1*g1 + a.x*g2 + a.y*g3 + a.z*g4 + a.w*g5 + rq1*g6;      \
    hx.z = lm1*g0 + a.x*g1 + a.y*g2 + a.z*g3 + a.w*g4 + rq1*g5 + rq2*g6;      \
    hx.w = a.x*g0 + a.y*g1 + a.z*g2 + a.w*g3 + rq1*g4 + rq2*g5 + rq3*g6;      \
    h[(J) % 7] = hx;                                                          \
    if (it >= 6) {                                                            \
        float4 o;                                                             \
        o.x = VERT(J, x); o.y = VERT(J, y);                                   \
        o.z = VERT(J, z); o.w = VERT(J, w);                                   \
        *(float4*)(outc + (size_t)(yh - 3) * NPIX + c) = o;                   \
    }                                                                         \
}

__global__ __launch_bounds__(256, 2) void conv_k(float* __restrict__ out) {
    const int lane = threadIdx.x & 31;
    const int wrp  = threadIdx.x >> 5;
    const int ch   = blockIdx.y;
    const int y0   = blockIdx.x * RB;
    const int c    = (wrp << 7) + (lane << 2);

    const float* __restrict__ cube = g_cube + (size_t)ch * (NPIX * NPIX);
    float* __restrict__ outc = out + (size_t)ch * (NPIX * NPIX);

    const float g0 = g_g1d[0], g1 = g_g1d[1], g2 = g_g1d[2], g3 = g_g1d[3],
                g4 = g_g1d[4], g5 = g_g1d[5], g6 = g_g1d[6];

    float4 h[7];
    float4 p[7];
    float4 hb[2];

    // ---- warmup: prefetch rows 0..6 (7 back-to-back LDGs) + halo row 0
    #pragma unroll
    for (int j = 0; j < 7; j++) {
        int yn = y0 - 3 + j;
        float4 np = make_float4(0.f, 0.f, 0.f, 0.f);
        if ((unsigned)yn < (unsigned)NPIX)
            np = *(const float4*)(cube + (size_t)yn * NPIX + c);
        p[j] = np;
    }
    {
        int yn = y0 - 3;
        float4 nh = make_float4(0.f, 0.f, 0.f, 0.f);
        if ((unsigned)yn < (unsigned)NPIX) {
            const float* rp = cube + (size_t)yn * NPIX;
            if (lane == 0  && c >= 4)        nh = *(const float4*)(rp + c - 4);
            if (lane == 31 && c + 7 < NPIX)  nh = *(const float4*)(rp + c + 4);
        }
        hb[0] = nh;
        hb[1] = make_float4(0.f, 0.f, 0.f, 0.f);
    }

    // ---- 70 steps = 5 chunks of 14 (both %7 and %2 rings compile-time)
    #pragma unroll 1
    for (int base = 0; base < RB + 6; base += 14) {
        CSTEP(0)  CSTEP(1)  CSTEP(2)  CSTEP(3)  CSTEP(4)  CSTEP(5)  CSTEP(6)
        CSTEP(7)  CSTEP(8)  CSTEP(9)  CSTEP(10) CSTEP(11) CSTEP(12) CSTEP(13)
    }
}

extern "C" void kernel_launch(void* const* d_in, const int* in_sizes, int n_in,
                              void* d_out, int out_size) {
    const float* pos = (const float*)d_in[0];   // pos_img (M,2)
    const float* vel = (const float*)d_in[1];   // vel_chan (M,)
    const float* flx = (const float*)d_in[2];   // flux (M,)
    const float* vax = (const float*)d_in[3];   // vel_axis (64,)
    const float* k2d = (const float*)d_in[4];   // kernel2d (49,)
    float* out = (float*)d_out;

    int M = in_sizes[1];

    zero_k<<<4736, 256>>>();
    prep_k<<<1, 32>>>(k2d);
    scatter_k<<<(M + 255) / 256, 256>>>(pos, vel, flx, vax, M);

    dim3 grid(NPIX / RB, NVCH);
    conv_k<<<grid, 256>>>(out);
}

// round 8
// speedup vs baseline: 1.2327x; 1.2327x over previous
#include <cuda_runtime.h>

#define NPIX 1024
#define NVCH 64
#define RB 128          // output rows per conv block

__device__ float g_cube[(size_t)NVCH * NPIX * NPIX];   // 256 MB scratch
__device__ float g_g1d[8];

// ---------------------------------------------------------------- zero cube
__global__ __launch_bounds__(256) void zero_k() {
    float4* p = reinterpret_cast<float4*>(g_cube);
    const int n4 = NVCH * NPIX * NPIX / 4;
    float4 z = make_float4(0.f, 0.f, 0.f, 0.f);
    for (int i = blockIdx.x * 256 + threadIdx.x; i < n4; i += gridDim.x * 256)
        p[i] = z;
}

// ------------------------------------------------- recover separable 1D taps
__global__ void prep_k(const float* __restrict__ k2d) {
    int k = threadIdx.x;
    if (k < 7) {
        float s = 0.f;
        #pragma unroll
        for (int j = 0; j < 7; j++) s += k2d[k * 7 + j];
        g_g1d[k] = s;
    }
}

// ---------------------------------------------------------------- scatter
__global__ __launch_bounds__(256) void scatter_k(
    const float* __restrict__ pos,
    const float* __restrict__ vel,
    const float* __restrict__ flx,
    const float* __restrict__ vax,
    int M)
{
    int i = blockIdx.x * 256 + threadIdx.x;
    if (i >= M) return;

    float2 p = reinterpret_cast<const float2*>(pos)[i];
    float v  = vel[i];
    float f  = flx[i];

    float vel0 = __ldg(&vax[0]);
    float dv   = __fsub_rn(__ldg(&vax[1]), vel0);

    const float FOVH = 51.15f;
    int ix = (int)floorf(__fmul_rn(__fadd_rn(p.x, FOVH), 10.0f));
    int iy = (int)floorf(__fmul_rn(__fadd_rn(p.y, FOVH), 10.0f));
    int iv = (int)floorf(__fdiv_rn(__fsub_rn(v, vel0), dv));

    if ((unsigned)(ix + 4) >= (unsigned)(NPIX + 8)) return;
    if ((unsigned)(iy + 4) >= (unsigned)(NPIX + 8)) return;
    if ((unsigned)iv >= (unsigned)NVCH) return;

    int flat = (iv * NPIX + iy) * NPIX + ix;
    if ((unsigned)flat < (unsigned)(NVCH * NPIX * NPIX))
        atomicAdd(&g_cube[flat], f);
}

// -------- register-streaming separable 7x7 conv, NO shuffles:
// each thread loads 3 overlapping float4s per row (c-4, c, c+4); the halo
// loads hit L1/L2 lines already streamed by neighbor lanes, so DRAM traffic
// is unchanged but every step is a pure load->FMA chain with 3 independent
// LDGs -> ptxas can batch loads across the unrolled chunk (MLP >> 1).

#define VERT(JJ, comp)                                                        \
    (g0*h[((JJ)+1)%7].comp + g1*h[((JJ)+2)%7].comp + g2*h[((JJ)+3)%7].comp +  \
     g3*h[((JJ)+4)%7].comp + g4*h[((JJ)+5)%7].comp + g5*h[((JJ)+6)%7].comp +  \
     g6*h[(JJ)%7].comp)

#define STEP(J, IT)                                                           \
{                                                                             \
    const int it = (IT);                                                      \
    const int yh = y0 - 3 + it;                                               \
    float4 a  = make_float4(0.f, 0.f, 0.f, 0.f);                              \
    float4 hl = a, hr = a;                                                    \
    if ((unsigned)yh < (unsigned)NPIX) {                                      \
        const float* rp = cube + (size_t)yh * NPIX;                           \
        a = *(const float4*)(rp + c);                                         \
        if (c >= 4)        hl = *(const float4*)(rp + c - 4);                 \
        if (c + 7 < NPIX)  hr = *(const float4*)(rp + c + 4);                 \
    }                                                                         \
    float4 hx;                                                                \
    hx.x = hl.y*g0 + hl.z*g1 + hl.w*g2 + a.x*g3 + a.y*g4 + a.z*g5 + a.w*g6;   \
    hx.y = hl.z*g0 + hl.w*g1 + a.x*g2 + a.y*g3 + a.z*g4 + a.w*g5 + hr.x*g6;   \
    hx.z = hl.w*g0 + a.x*g1 + a.y*g2 + a.z*g3 + a.w*g4 + hr.x*g5 + hr.y*g6;   \
    hx.w = a.x*g0 + a.y*g1 + a.z*g2 + a.w*g3 + hr.x*g4 + hr.y*g5 + hr.z*g6;   \
    h[(J)%7] = hx;                                                            \
    if (it >= 6) {                                                            \
        float4 o;                                                             \
        o.x = VERT(J, x); o.y = VERT(J, y);                                   \
        o.z = VERT(J, z); o.w = VERT(J, w);                                   \
        *(float4*)(outc + (size_t)(yh - 3) * NPIX + c) = o;                   \
    }                                                                         \
}

__global__ __launch_bounds__(256, 3) void conv_k(float* __restrict__ out) {
    const int lane = threadIdx.x & 31;
    const int wrp  = threadIdx.x >> 5;
    const int ch   = blockIdx.y;
    const int y0   = blockIdx.x * RB;
    const int c    = (wrp << 7) + (lane << 2);      // global column base (x4)

    const float* __restrict__ cube = g_cube + (size_t)ch * (NPIX * NPIX);
    float* __restrict__ outc = out + (size_t)ch * (NPIX * NPIX);

    const float g0 = g_g1d[0], g1 = g_g1d[1], g2 = g_g1d[2], g3 = g_g1d[3],
                g4 = g_g1d[4], g5 = g_g1d[5], g6 = g_g1d[6];

    float4 h[7];

    // RB+6 = 134 producer rows: 19 chunks of 7 (it 0..132) + tail (it 133)
    #pragma unroll 1
    for (int base = 0; base < RB + 5; base += 7) {
        STEP(0, base + 0)
        STEP(1, base + 1)
        STEP(2, base + 2)
        STEP(3, base + 3)
        STEP(4, base + 4)
        STEP(5, base + 5)
        STEP(6, base + 6)
    }
    STEP(0, RB + 5)     // it = 133, slot 133%7 == 0
}

extern "C" void kernel_launch(void* const* d_in, const int* in_sizes, int n_in,
                              void* d_out, int out_size) {
    const float* pos = (const float*)d_in[0];   // pos_img (M,2)
    const float* vel = (const float*)d_in[1];   // vel_chan (M,)
    const float* flx = (const float*)d_in[2];   // flux (M,)
    const float* vax = (const float*)d_in[3];   // vel_axis (64,)
    const float* k2d = (const float*)d_in[4];   // kernel2d (49,)
    float* out = (float*)d_out;

    int M = in_sizes[1];

    zero_k<<<4736, 256>>>();
    prep_k<<<1, 32>>>(k2d);
    scatter_k<<<(M + 255) / 256, 256>>>(pos, vel, flx, vax, M);

    dim3 grid(NPIX / RB, NVCH);
    conv_k<<<grid, 256>>>(out);
}